// round 3
// baseline (speedup 1.0000x reference)
#include <cuda_runtime.h>
#include <cstddef>

#define T_STEPS 100
#define BATCH   1024
#define HS      128
#define G4      512
#define INSZ    3
#define INITSZ  268
#define NBNECK  256
#define NPC     256
#define NHD     12

typedef unsigned long long u64;

// ---------- packed f32x2 helpers (sm_100+ FFMA2 via PTX) ----------
__device__ __forceinline__ u64 pk2(float lo, float hi) {
    u64 r; asm("mov.b64 %0,{%1,%2};" : "=l"(r) : "f"(lo), "f"(hi)); return r;
}
__device__ __forceinline__ void upk2(u64 v, float& lo, float& hi) {
    asm("mov.b64 {%0,%1},%2;" : "=f"(lo), "=f"(hi) : "l"(v));
}
__device__ __forceinline__ u64 fma2(u64 a, u64 b, u64 c) {
    u64 d; asm("fma.rn.f32x2 %0,%1,%2,%3;" : "=l"(d) : "l"(a), "l"(b), "l"(c)); return d;
}
__device__ __forceinline__ float sigf(float x) { return 1.0f / (1.0f + __expf(-x)); }

// =====================================================================
// Kernel 1: LSTM recurrence. 128 blocks x 256 threads, 8 batch rows per
// block (4 row-pairs packed into f32x2 lanes). U double-buffered through
// smem in 32-k-row chunks (64KB each): chunk kc+1 loads are issued before
// computing on chunk kc, hiding the L2 latency. h kept in smem
// (pair-packed), c in registers. Writes rnn_states / rnn_cells.
// =====================================================================
// dyn smem floats: U0[32*512] | U1[32*512] | hp[128*4*2] | Wsm[3*512] | xsm[24]
#define K1_UCH   (32 * G4)            // 16384 floats per buffer
#define K1_HP    (HS * 4 * 2)         // 1024 floats (u64-viewed pairs)
#define K1_W     (INSZ * G4)          // 1536
#define K1_X     24
#define K1_SMEMF (2 * K1_UCH + K1_HP + K1_W + K1_X)
#define K1_SMEMB (K1_SMEMF * 4)       // ~139 KB

__global__ void __launch_bounds__(256) lstm_kernel(
    const float* __restrict__ x, const float* __restrict__ ic,
    const float* __restrict__ W, const float* __restrict__ U, const float* __restrict__ b,
    const float* __restrict__ W_ih, const float* __restrict__ b_ih,
    const float* __restrict__ W_ic, const float* __restrict__ b_ic,
    float* __restrict__ out_h, float* __restrict__ out_c)
{
    extern __shared__ float sm[];
    float* Ubuf[2];
    Ubuf[0] = sm;
    Ubuf[1] = sm + K1_UCH;
    u64*   hpu = (u64*)(sm + 2 * K1_UCH);      // hpu[k*4 + pair]
    float* Wsm = sm + 2 * K1_UCH + K1_HP;
    float* xsm = Wsm + K1_W;

    const int tid = threadIdx.x;
    const int jj  = tid & 127;      // gate column within 128
    const int rh  = tid >> 7;       // row-half: pairs {2rh, 2rh+1}
    const int r0  = blockIdx.x * 8; // first global batch row of this block

    // stage W (3x512)
    for (int i = tid; i < K1_W; i += 256) Wsm[i] = W[i];
    // stage this block's init_conds rows into Ubuf[0] (scratch)
    for (int i = tid; i < 8 * INITSZ; i += 256) {
        int r = i / INITSZ, k = i - r * INITSZ;
        Ubuf[0][i] = ic[(size_t)(r0 + r) * INITSZ + k];
    }
    u64 bias2[4];
#pragma unroll
    for (int g = 0; g < 4; g++) { float bv = b[g * 128 + jj]; bias2[g] = pk2(bv, bv); }
    __syncthreads();

    // h0 = ic @ W_ih + b_ih ; c0 = ic @ W_ic + b_ic   (for this thread's 4 rows)
    u64 cst[2];
    {
        u64 ah[2], ac[2];
        float bihv = b_ih[jj], bicv = b_ic[jj];
        ah[0] = ah[1] = pk2(bihv, bihv);
        ac[0] = ac[1] = pk2(bicv, bicv);
        for (int k = 0; k < INITSZ; k++) {
            float wih = W_ih[k * 128 + jj];
            float wic = W_ic[k * 128 + jj];
            u64 w2h = pk2(wih, wih), w2c = pk2(wic, wic);
#pragma unroll
            for (int p2 = 0; p2 < 2; p2++) {
                int p = 2 * rh + p2;
                u64 icp = pk2(Ubuf[0][(2 * p) * INITSZ + k], Ubuf[0][(2 * p + 1) * INITSZ + k]);
                ah[p2] = fma2(icp, w2h, ah[p2]);
                ac[p2] = fma2(icp, w2c, ac[p2]);
            }
        }
        __syncthreads();   // all ic reads done before Ubuf[0] gets re-staged with U
#pragma unroll
        for (int p2 = 0; p2 < 2; p2++) {
            int p = 2 * rh + p2;
            hpu[jj * 4 + p] = ah[p2];
            cst[p2] = ac[p2];
        }
    }

    // prologue: load U chunk 0 into buffer 0
    {
        const float4* Ug  = (const float4*)(U);
        float4*       Us4 = (float4*)Ubuf[0];
#pragma unroll
        for (int it = 0; it < 16; it++) Us4[tid + 256 * it] = Ug[tid + 256 * it];
    }

    for (int t = 0; t < T_STEPS; t++) {
        if (tid < 24) {
            int r = tid / 3, i = tid - r * 3;
            xsm[tid] = x[((size_t)t * BATCH + r0 + r) * INSZ + i];
        }
        __syncthreads();  // xsm + U chunk(cur) ready; prev-step hp writes visible

        u64 acc[2][4];
#pragma unroll
        for (int p2 = 0; p2 < 2; p2++)
#pragma unroll
            for (int g = 0; g < 4; g++) acc[p2][g] = bias2[g];

        // + x_t @ W
#pragma unroll
        for (int p2 = 0; p2 < 2; p2++) {
            int p = 2 * rh + p2;
#pragma unroll
            for (int i = 0; i < 3; i++) {
                u64 xp = pk2(xsm[(2 * p) * 3 + i], xsm[(2 * p + 1) * 3 + i]);
#pragma unroll
                for (int g = 0; g < 4; g++) {
                    float wv = Wsm[i * G4 + g * 128 + jj];
                    acc[p2][g] = fma2(xp, pk2(wv, wv), acc[p2][g]);
                }
            }
        }

        // + h @ U : double-buffered chunks of 32 k-rows.
        // At iteration kc: buffer kc&1 holds chunk kc (guaranteed by the
        // barrier at the end of the previous iteration / top of step).
        // Issue loads of the NEXT chunk into the other buffer first, then
        // compute — the loads' latency hides under 128 fma2 iterations.
        for (int kc = 0; kc < 4; kc++) {
            const int cur = kc & 1;
            const int nxt = cur ^ 1;
            // prefetch next chunk (chunk kc+1 for kc<3; chunk 0 for the
            // next time-step when kc==3 — same data every step, cheap L2 hit)
            {
                const int kc_next = (kc < 3) ? (kc + 1) : 0;
                const float4* Ug  = (const float4*)(U + (size_t)kc_next * 32 * G4);
                float4*       Us4 = (float4*)Ubuf[nxt];
#pragma unroll
                for (int it = 0; it < 16; it++) Us4[tid + 256 * it] = Ug[tid + 256 * it];
            }
            const float* Usm = Ubuf[cur];
#pragma unroll 4
            for (int k = 0; k < 32; k++) {
                int kg = kc * 32 + k;
                u64 hAp = hpu[kg * 4 + 2 * rh];
                u64 hBp = hpu[kg * 4 + 2 * rh + 1];
#pragma unroll
                for (int g = 0; g < 4; g++) {
                    float uv = Usm[k * G4 + g * 128 + jj];
                    u64 u2 = pk2(uv, uv);
                    acc[0][g] = fma2(hAp, u2, acc[0][g]);
                    acc[1][g] = fma2(hBp, u2, acc[1][g]);
                }
            }
            __syncthreads();  // next chunk landed; cur buffer free for reuse
        }
        // NOTE: after kc==3 the barrier also guarantees chunk 0 is resident
        // in buffer 0 for the next time-step, and that all hp reads are done.

        // gate nonlinearities + state update + outputs
#pragma unroll
        for (int p2 = 0; p2 < 2; p2++) {
            int p = 2 * rh + p2;
            float iA, iB, fA, fB, gA, gB, oA, oB, cA, cB;
            upk2(acc[p2][0], iA, iB);
            upk2(acc[p2][1], fA, fB);
            upk2(acc[p2][2], gA, gB);
            upk2(acc[p2][3], oA, oB);
            upk2(cst[p2], cA, cB);
            iA = sigf(iA); iB = sigf(iB);
            fA = sigf(fA); fB = sigf(fB);
            gA = tanhf(gA); gB = tanhf(gB);
            oA = sigf(oA); oB = sigf(oB);
            cA = fA * cA + iA * gA;
            cB = fB * cB + iB * gB;
            float hA = oA * tanhf(cA);
            float hB = oB * tanhf(cB);
            cst[p2] = pk2(cA, cB);
            hpu[jj * 4 + p] = pk2(hA, hB);
            size_t baseA = ((size_t)t * BATCH + r0 + 2 * p) * HS + jj;
            size_t baseB = baseA + HS;
            out_h[baseA] = hA; out_h[baseB] = hB;
            out_c[baseA] = cA; out_c[baseB] = cB;
        }
    }
}

// =====================================================================
// Kernel 2: heads. 1600 blocks x 256 threads, 64 rows per block.
// f32x2 packed over OUTPUT COLUMN pairs (so H stays row-major: broadcast
// LDS for h, float2 weight loads). bn tile kept in smem for pc/hd.
// =====================================================================
#define K2_TILE  64
#define K2_SMEMF (K2_TILE * HS + K2_TILE * NBNECK)   // 8192 + 16384
#define K2_SMEMB (K2_SMEMF * 4)

__global__ void __launch_bounds__(256) heads_kernel(
    const float* __restrict__ Hin,
    const float* __restrict__ W_bn, const float* __restrict__ W_pc,
    const float* __restrict__ b_pc, const float* __restrict__ W_hd,
    const float* __restrict__ b_hd,
    float* __restrict__ out_hd, float* __restrict__ out_pc, float* __restrict__ out_bn)
{
    extern __shared__ float sm[];
    float* hs  = sm;                 // [64][128]
    float* bns = sm + K2_TILE * HS;  // [64][256]
    const int tid = threadIdx.x;
    const int rg  = tid >> 5;   // warp id = row group (8 rows each)
    const int cg  = tid & 31;   // 8 output columns each (4 f32x2 pairs)
    const size_t tb0 = (size_t)blockIdx.x * K2_TILE;

    // stage H tile (coalesced, conflict-free)
    {
        const float4* g4 = (const float4*)(Hin + tb0 * HS);
        float4*       s4 = (float4*)hs;
#pragma unroll
        for (int it = 0; it < 8; it++) s4[tid + 256 * it] = g4[tid + 256 * it];
    }
    __syncthreads();

    u64 acc[8][4];

    // ---- BN = H @ W_bn (no bias) ----
#pragma unroll
    for (int r = 0; r < 8; r++)
#pragma unroll
        for (int c = 0; c < 4; c++) acc[r][c] = 0ull;

    for (int k = 0; k < HS; k++) {
        float hv[8];
#pragma unroll
        for (int r = 0; r < 8; r++) hv[r] = hs[(rg * 8 + r) * HS + k];
        const u64* wrow = (const u64*)(W_bn + (size_t)k * NBNECK + cg * 8);
        u64 w0 = wrow[0], w1 = wrow[1], w2 = wrow[2], w3 = wrow[3];
#pragma unroll
        for (int r = 0; r < 8; r++) {
            u64 h2 = pk2(hv[r], hv[r]);
            acc[r][0] = fma2(h2, w0, acc[r][0]);
            acc[r][1] = fma2(h2, w1, acc[r][1]);
            acc[r][2] = fma2(h2, w2, acc[r][2]);
            acc[r][3] = fma2(h2, w3, acc[r][3]);
        }
    }
#pragma unroll
    for (int r = 0; r < 8; r++) {
        int row = rg * 8 + r;
        u64* bsr = (u64*)(bns + row * NBNECK + cg * 8);
        u64* gor = (u64*)(out_bn + (tb0 + row) * NBNECK + cg * 8);
#pragma unroll
        for (int c = 0; c < 4; c++) { bsr[c] = acc[r][c]; gor[c] = acc[r][c]; }
    }
    __syncthreads();

    // ---- PC = BN @ W_pc + b_pc ----
    {
        const u64* bp = (const u64*)(b_pc + cg * 8);
        u64 bias[4] = { bp[0], bp[1], bp[2], bp[3] };
#pragma unroll
        for (int r = 0; r < 8; r++)
#pragma unroll
            for (int c = 0; c < 4; c++) acc[r][c] = bias[c];
    }
    for (int k = 0; k < NBNECK; k++) {
        float hv[8];
#pragma unroll
        for (int r = 0; r < 8; r++) hv[r] = bns[(rg * 8 + r) * NBNECK + k];
        const u64* wrow = (const u64*)(W_pc + (size_t)k * NPC + cg * 8);
        u64 w0 = wrow[0], w1 = wrow[1], w2 = wrow[2], w3 = wrow[3];
#pragma unroll
        for (int r = 0; r < 8; r++) {
            u64 h2 = pk2(hv[r], hv[r]);
            acc[r][0] = fma2(h2, w0, acc[r][0]);
            acc[r][1] = fma2(h2, w1, acc[r][1]);
            acc[r][2] = fma2(h2, w2, acc[r][2]);
            acc[r][3] = fma2(h2, w3, acc[r][3]);
        }
    }
#pragma unroll
    for (int r = 0; r < 8; r++) {
        int row = rg * 8 + r;
        u64* gor = (u64*)(out_pc + (tb0 + row) * NPC + cg * 8);
#pragma unroll
        for (int c = 0; c < 4; c++) gor[c] = acc[r][c];
    }

    // ---- HD = BN @ W_hd + b_hd (warp-per-row, lane-split over k) ----
#pragma unroll 1
    for (int rr = 0; rr < 8; rr++) {
        int row = rg + rr * 8;
        float pacc[NHD];
#pragma unroll
        for (int c = 0; c < NHD; c++) pacc[c] = 0.0f;
#pragma unroll
        for (int m = 0; m < 8; m++) {
            int k = cg + m * 32;
            float bv = bns[row * NBNECK + k];
            const float* wh = W_hd + k * NHD;
#pragma unroll
            for (int c = 0; c < NHD; c++) pacc[c] += bv * wh[c];
        }
#pragma unroll
        for (int c = 0; c < NHD; c++) {
            float v = pacc[c];
#pragma unroll
            for (int off = 16; off; off >>= 1) v += __shfl_xor_sync(0xffffffffu, v, off);
            if (cg == 0) out_hd[(tb0 + row) * NHD + c] = v + b_hd[c];
        }
    }
}

// =====================================================================
extern "C" void kernel_launch(void* const* d_in, const int* in_sizes, int n_in,
                              void* d_out, int out_size) {
    (void)in_sizes; (void)n_in; (void)out_size;
    const float* x    = (const float*)d_in[0];
    const float* ic   = (const float*)d_in[1];
    const float* W    = (const float*)d_in[2];
    const float* U    = (const float*)d_in[3];
    const float* b    = (const float*)d_in[4];
    const float* W_ih = (const float*)d_in[5];
    const float* b_ih = (const float*)d_in[6];
    const float* W_ic = (const float*)d_in[7];
    const float* b_ic = (const float*)d_in[8];
    const float* W_bn = (const float*)d_in[9];
    const float* W_pc = (const float*)d_in[10];
    const float* b_pc = (const float*)d_in[11];
    const float* W_hd = (const float*)d_in[12];
    const float* b_hd = (const float*)d_in[13];

    float* out = (float*)d_out;
    const size_t TB = (size_t)T_STEPS * BATCH;
    float* out_hd = out;
    float* out_pc = out_hd + TB * NHD;
    float* out_bn = out_pc + TB * NPC;
    float* out_h  = out_bn + TB * NBNECK;
    float* out_c  = out_h  + TB * HS;

    cudaFuncSetAttribute(lstm_kernel,  cudaFuncAttributeMaxDynamicSharedMemorySize, K1_SMEMB);
    cudaFuncSetAttribute(heads_kernel, cudaFuncAttributeMaxDynamicSharedMemorySize, K2_SMEMB);

    lstm_kernel<<<BATCH / 8, 256, K1_SMEMB>>>(x, ic, W, U, b, W_ih, b_ih, W_ic, b_ic,
                                              out_h, out_c);
    heads_kernel<<<(int)(TB / K2_TILE), 256, K2_SMEMB>>>(out_h, W_bn, W_pc, b_pc, W_hd, b_hd,
                                                         out_hd, out_pc, out_bn);
}

// round 4
// speedup vs baseline: 1.3907x; 1.3907x over previous
#include <cuda_runtime.h>
#include <cstddef>
#include <cstdint>

#define T_STEPS 100
#define BATCH   1024
#define HS      128
#define G4      512
#define INSZ    3
#define INITSZ  268
#define NBNECK  256
#define NPC     256
#define NHD     12

typedef unsigned long long u64;

// ---------- packed f32x2 helpers (sm_100+ FFMA2 via PTX) ----------
__device__ __forceinline__ u64 pk2(float lo, float hi) {
    u64 r; asm("mov.b64 %0,{%1,%2};" : "=l"(r) : "f"(lo), "f"(hi)); return r;
}
__device__ __forceinline__ void upk2(u64 v, float& lo, float& hi) {
    asm("mov.b64 {%0,%1},%2;" : "=f"(lo), "=f"(hi) : "l"(v));
}
__device__ __forceinline__ u64 fma2(u64 a, u64 b, u64 c) {
    u64 d; asm("fma.rn.f32x2 %0,%1,%2,%3;" : "=l"(d) : "l"(a), "l"(b), "l"(c)); return d;
}
__device__ __forceinline__ float sigf(float x) { return 1.0f / (1.0f + __expf(-x)); }

// ---------- cp.async helpers ----------
__device__ __forceinline__ void cp_async16(uint32_t saddr, const void* gaddr) {
    asm volatile("cp.async.cg.shared.global [%0], [%1], 16;\n" :: "r"(saddr), "l"(gaddr));
}
__device__ __forceinline__ void cp_commit() { asm volatile("cp.async.commit_group;\n"); }
__device__ __forceinline__ void cp_wait0()  { asm volatile("cp.async.wait_group 0;\n" ::: "memory"); }

// =====================================================================
// Kernel 1: LSTM recurrence. 128 blocks x 256 threads, 8 batch rows per
// block (4 row-pairs packed into f32x2 lanes). U double-buffered through
// smem in 32-k-row chunks (64KB each) via cp.async (no reg roundtrip, no
// STS drain at barriers). h kept in smem (pair-packed), c in registers.
// =====================================================================
#define K1_UCH   (32 * G4)            // 16384 floats per buffer
#define K1_HP    (HS * 4 * 2)         // 1024 floats (u64-viewed pairs)
#define K1_W     (INSZ * G4)          // 1536
#define K1_X     24
#define K1_SMEMF (2 * K1_UCH + K1_HP + K1_W + K1_X)
#define K1_SMEMB (K1_SMEMF * 4)       // ~139 KB

__global__ void __launch_bounds__(256) lstm_kernel(
    const float* __restrict__ x, const float* __restrict__ ic,
    const float* __restrict__ W, const float* __restrict__ U, const float* __restrict__ b,
    const float* __restrict__ W_ih, const float* __restrict__ b_ih,
    const float* __restrict__ W_ic, const float* __restrict__ b_ic,
    float* __restrict__ out_h, float* __restrict__ out_c)
{
    extern __shared__ float sm[];
    float* Ubuf[2];
    Ubuf[0] = sm;
    Ubuf[1] = sm + K1_UCH;
    u64*   hpu = (u64*)(sm + 2 * K1_UCH);      // hpu[k*4 + pair]
    float* Wsm = sm + 2 * K1_UCH + K1_HP;
    float* xsm = Wsm + K1_W;

    const int tid = threadIdx.x;
    const int jj  = tid & 127;      // gate column within 128
    const int rh  = tid >> 7;       // row-half: pairs {2rh, 2rh+1}
    const int r0  = blockIdx.x * 8; // first global batch row of this block

    uint32_t sU[2];
    sU[0] = (uint32_t)__cvta_generic_to_shared(Ubuf[0]);
    sU[1] = (uint32_t)__cvta_generic_to_shared(Ubuf[1]);

    // stage W (3x512)
    for (int i = tid; i < K1_W; i += 256) Wsm[i] = W[i];
    // stage this block's init_conds rows into Ubuf[0] (scratch)
    for (int i = tid; i < 8 * INITSZ; i += 256) {
        int r = i / INITSZ, k = i - r * INITSZ;
        Ubuf[0][i] = ic[(size_t)(r0 + r) * INITSZ + k];
    }
    u64 bias2[4];
#pragma unroll
    for (int g = 0; g < 4; g++) { float bv = b[g * 128 + jj]; bias2[g] = pk2(bv, bv); }
    __syncthreads();

    // h0 = ic @ W_ih + b_ih ; c0 = ic @ W_ic + b_ic   (for this thread's 4 rows)
    u64 cst[2];
    {
        u64 ah[2], ac[2];
        float bihv = b_ih[jj], bicv = b_ic[jj];
        ah[0] = ah[1] = pk2(bihv, bihv);
        ac[0] = ac[1] = pk2(bicv, bicv);
        for (int k = 0; k < INITSZ; k++) {
            float wih = W_ih[k * 128 + jj];
            float wic = W_ic[k * 128 + jj];
            u64 w2h = pk2(wih, wih), w2c = pk2(wic, wic);
#pragma unroll
            for (int p2 = 0; p2 < 2; p2++) {
                int p = 2 * rh + p2;
                u64 icp = pk2(Ubuf[0][(2 * p) * INITSZ + k], Ubuf[0][(2 * p + 1) * INITSZ + k]);
                ah[p2] = fma2(icp, w2h, ah[p2]);
                ac[p2] = fma2(icp, w2c, ac[p2]);
            }
        }
        __syncthreads();   // all ic reads done before Ubuf[0] is re-staged with U
#pragma unroll
        for (int p2 = 0; p2 < 2; p2++) {
            int p = 2 * rh + p2;
            hpu[jj * 4 + p] = ah[p2];
            cst[p2] = ac[p2];
        }
    }

    // prologue: cp.async U chunk 0 into buffer 0
    {
        const float4* Ug = (const float4*)(U);
#pragma unroll
        for (int it = 0; it < 16; it++)
            cp_async16(sU[0] + (tid + 256 * it) * 16, Ug + tid + 256 * it);
        cp_commit();
        cp_wait0();
    }

    for (int t = 0; t < T_STEPS; t++) {
        if (tid < 24) {
            int r = tid / 3, i = tid - r * 3;
            xsm[tid] = x[((size_t)t * BATCH + r0 + r) * INSZ + i];
        }
        __syncthreads();  // xsm + U chunk(cur) ready; prev-step hp writes visible

        u64 acc[2][4];
#pragma unroll
        for (int p2 = 0; p2 < 2; p2++)
#pragma unroll
            for (int g = 0; g < 4; g++) acc[p2][g] = bias2[g];

        // + x_t @ W
#pragma unroll
        for (int p2 = 0; p2 < 2; p2++) {
            int p = 2 * rh + p2;
#pragma unroll
            for (int i = 0; i < 3; i++) {
                u64 xp = pk2(xsm[(2 * p) * 3 + i], xsm[(2 * p + 1) * 3 + i]);
#pragma unroll
                for (int g = 0; g < 4; g++) {
                    float wv = Wsm[i * G4 + g * 128 + jj];
                    acc[p2][g] = fma2(xp, pk2(wv, wv), acc[p2][g]);
                }
            }
        }

        // + h @ U : double-buffered 32-k-row chunks via cp.async.
        for (int kc = 0; kc < 4; kc++) {
            const int cur = kc & 1;
            const int nxt = cur ^ 1;
            {   // prefetch next chunk (chunk 0 again when kc==3, for next step)
                const int kc_next = (kc < 3) ? (kc + 1) : 0;
                const float4* Ug = (const float4*)(U + (size_t)kc_next * 32 * G4);
#pragma unroll
                for (int it = 0; it < 16; it++)
                    cp_async16(sU[nxt] + (tid + 256 * it) * 16, Ug + tid + 256 * it);
                cp_commit();
            }
            const float* Usm = Ubuf[cur];
#pragma unroll 4
            for (int k = 0; k < 32; k++) {
                int kg = kc * 32 + k;
                u64 hAp = hpu[kg * 4 + 2 * rh];
                u64 hBp = hpu[kg * 4 + 2 * rh + 1];
#pragma unroll
                for (int g = 0; g < 4; g++) {
                    float uv = Usm[k * G4 + g * 128 + jj];
                    u64 u2 = pk2(uv, uv);
                    acc[0][g] = fma2(hAp, u2, acc[0][g]);
                    acc[1][g] = fma2(hBp, u2, acc[1][g]);
                }
            }
            cp_wait0();
            __syncthreads();  // next chunk landed; cur buffer free for reuse
        }

        // gate nonlinearities + state update + outputs
#pragma unroll
        for (int p2 = 0; p2 < 2; p2++) {
            int p = 2 * rh + p2;
            float iA, iB, fA, fB, gA, gB, oA, oB, cA, cB;
            upk2(acc[p2][0], iA, iB);
            upk2(acc[p2][1], fA, fB);
            upk2(acc[p2][2], gA, gB);
            upk2(acc[p2][3], oA, oB);
            upk2(cst[p2], cA, cB);
            iA = sigf(iA); iB = sigf(iB);
            fA = sigf(fA); fB = sigf(fB);
            gA = tanhf(gA); gB = tanhf(gB);
            oA = sigf(oA); oB = sigf(oB);
            cA = fA * cA + iA * gA;
            cB = fB * cB + iB * gB;
            float hA = oA * tanhf(cA);
            float hB = oB * tanhf(cB);
            cst[p2] = pk2(cA, cB);
            hpu[jj * 4 + p] = pk2(hA, hB);
            size_t baseA = ((size_t)t * BATCH + r0 + 2 * p) * HS + jj;
            size_t baseB = baseA + HS;
            out_h[baseA] = hA; out_h[baseB] = hB;
            out_c[baseA] = cA; out_c[baseB] = cB;
        }
    }
}

// =====================================================================
// Kernel 2: heads, v2 — FMA-bound layout.
// 1600 blocks x 256 threads, 64 rows (=32 row-pairs) per block.
// f32x2 packed over ROW PAIRS; each thread owns 4 CONTIGUOUS cols
// (warp = 512B contiguous LDG.128 of weights -> 4 L1 wavefronts/k).
// h and bn stored pair-packed u64 in smem; broadcast LDS.64 per pair.
// Per k per warp: 1 LDG.128 + 8 bcast LDS + 32 fma2  ==> fma-bound.
// =====================================================================
#define K2_NP     32                  // row pairs per tile
#define K2_HPSTR  130                 // u64 stride of hp rows (k=128, padded even)
#define K2_BNSTR  258                 // u64 stride of bnp rows (k2=256, padded even)
#define K2_SMEMU  (K2_NP * K2_HPSTR + K2_NP * K2_BNSTR)   // u64 count = 12416
#define K2_SMEMB  (K2_SMEMU * 8)                          // 99328 B

__global__ void __launch_bounds__(256) heads_kernel(
    const float* __restrict__ Hin,
    const float* __restrict__ W_bn, const float* __restrict__ W_pc,
    const float* __restrict__ b_pc, const float* __restrict__ W_hd,
    const float* __restrict__ b_hd,
    float* __restrict__ out_hd, float* __restrict__ out_pc, float* __restrict__ out_bn)
{
    extern __shared__ u64 smu[];
    u64* hp  = smu;                       // hp[pair*130 + k]
    u64* bnp = smu + K2_NP * K2_HPSTR;    // bnp[pair*258 + k2]

    const int tid  = threadIdx.x;
    const int w    = tid >> 5;
    const int lane = tid & 31;
    const int rg2  = w >> 1;              // 0..3 : pairs rg2*8 .. +8
    const int cgp  = w & 1;               // col half: 0/1
    const int colb = cgp * 128 + lane * 4;
    const size_t tb0 = (size_t)blockIdx.x * 64;

    // ---- stage H tile as row-pairs: hp[pair*130+k] = pk2(H[2p][k], H[2p+1][k])
    {
        const int pair = tid >> 3;        // 0..31
        const int seg  = tid & 7;         // k segment of 16
        const float4* rA = (const float4*)(Hin + (tb0 + 2 * pair) * HS);
        const float4* rB = (const float4*)(Hin + (tb0 + 2 * pair + 1) * HS);
#pragma unroll
        for (int i = 0; i < 4; i++) {
            float4 a = rA[seg * 4 + i];
            float4 b = rB[seg * 4 + i];
            int k = seg * 16 + i * 4;
            u64* d = &hp[pair * K2_HPSTR + k];
            d[0] = pk2(a.x, b.x); d[1] = pk2(a.y, b.y);
            d[2] = pk2(a.z, b.z); d[3] = pk2(a.w, b.w);
        }
    }
    __syncthreads();

    u64 acc[8][4];

    // ---- BN = H @ W_bn (no bias) ----
#pragma unroll
    for (int p = 0; p < 8; p++)
#pragma unroll
        for (int c = 0; c < 4; c++) acc[p][c] = 0ull;

    for (int k = 0; k < HS; k++) {
        float4 wv = *(const float4*)(W_bn + (size_t)k * NBNECK + colb);
        u64 w0 = pk2(wv.x, wv.x), w1 = pk2(wv.y, wv.y);
        u64 w2 = pk2(wv.z, wv.z), w3 = pk2(wv.w, wv.w);
        const u64* hrow = &hp[(rg2 * 8) * K2_HPSTR + k];
#pragma unroll
        for (int p = 0; p < 8; p++) {
            u64 h2 = hrow[p * K2_HPSTR];
            acc[p][0] = fma2(h2, w0, acc[p][0]);
            acc[p][1] = fma2(h2, w1, acc[p][1]);
            acc[p][2] = fma2(h2, w2, acc[p][2]);
            acc[p][3] = fma2(h2, w3, acc[p][3]);
        }
    }
    // write bnp (pair-packed) + out_bn (unpacked rows)
#pragma unroll
    for (int p = 0; p < 8; p++) {
        int pr = rg2 * 8 + p;
        u64* d = &bnp[pr * K2_BNSTR + colb];
        d[0] = acc[p][0]; d[1] = acc[p][1]; d[2] = acc[p][2]; d[3] = acc[p][3];
        float lo0, hi0, lo1, hi1, lo2, hi2, lo3, hi3;
        upk2(acc[p][0], lo0, hi0); upk2(acc[p][1], lo1, hi1);
        upk2(acc[p][2], lo2, hi2); upk2(acc[p][3], lo3, hi3);
        float4* oA = (float4*)(out_bn + (tb0 + 2 * pr) * NBNECK + colb);
        float4* oB = (float4*)(out_bn + (tb0 + 2 * pr + 1) * NBNECK + colb);
        *oA = make_float4(lo0, lo1, lo2, lo3);
        *oB = make_float4(hi0, hi1, hi2, hi3);
    }
    __syncthreads();

    // ---- PC = BN @ W_pc + b_pc ----
    {
        float4 bv = *(const float4*)(b_pc + colb);
        u64 b0 = pk2(bv.x, bv.x), b1 = pk2(bv.y, bv.y);
        u64 b2 = pk2(bv.z, bv.z), b3 = pk2(bv.w, bv.w);
#pragma unroll
        for (int p = 0; p < 8; p++) {
            acc[p][0] = b0; acc[p][1] = b1; acc[p][2] = b2; acc[p][3] = b3;
        }
    }
    for (int k = 0; k < NBNECK; k++) {
        float4 wv = *(const float4*)(W_pc + (size_t)k * NPC + colb);
        u64 w0 = pk2(wv.x, wv.x), w1 = pk2(wv.y, wv.y);
        u64 w2 = pk2(wv.z, wv.z), w3 = pk2(wv.w, wv.w);
        const u64* brow = &bnp[(rg2 * 8) * K2_BNSTR + k];
#pragma unroll
        for (int p = 0; p < 8; p++) {
            u64 h2 = brow[p * K2_BNSTR];
            acc[p][0] = fma2(h2, w0, acc[p][0]);
            acc[p][1] = fma2(h2, w1, acc[p][1]);
            acc[p][2] = fma2(h2, w2, acc[p][2]);
            acc[p][3] = fma2(h2, w3, acc[p][3]);
        }
    }
#pragma unroll
    for (int p = 0; p < 8; p++) {
        int pr = rg2 * 8 + p;
        float lo0, hi0, lo1, hi1, lo2, hi2, lo3, hi3;
        upk2(acc[p][0], lo0, hi0); upk2(acc[p][1], lo1, hi1);
        upk2(acc[p][2], lo2, hi2); upk2(acc[p][3], lo3, hi3);
        float4* oA = (float4*)(out_pc + (tb0 + 2 * pr) * NPC + colb);
        float4* oB = (float4*)(out_pc + (tb0 + 2 * pr + 1) * NPC + colb);
        *oA = make_float4(lo0, lo1, lo2, lo3);
        *oB = make_float4(hi0, hi1, hi2, hi3);
    }

    // ---- HD = BN @ W_hd + b_hd (warp-per-8-rows, lane-split over k2) ----
#pragma unroll 1
    for (int rr = 0; rr < 8; rr++) {
        int row = w * 8 + rr;
        int p   = row >> 1;
        int sel = row & 1;
        float pacc[NHD];
#pragma unroll
        for (int c = 0; c < NHD; c++) pacc[c] = 0.0f;
#pragma unroll
        for (int m = 0; m < 8; m++) {
            int k2 = lane + m * 32;
            float lo, hi;
            upk2(bnp[p * K2_BNSTR + k2], lo, hi);
            float bv = sel ? hi : lo;
            const float* wh = W_hd + k2 * NHD;
#pragma unroll
            for (int c = 0; c < NHD; c++) pacc[c] += bv * wh[c];
        }
#pragma unroll
        for (int c = 0; c < NHD; c++) {
            float v = pacc[c];
#pragma unroll
            for (int off = 16; off; off >>= 1) v += __shfl_xor_sync(0xffffffffu, v, off);
            if (lane == 0) out_hd[(tb0 + row) * NHD + c] = v + b_hd[c];
        }
    }
}

// =====================================================================
extern "C" void kernel_launch(void* const* d_in, const int* in_sizes, int n_in,
                              void* d_out, int out_size) {
    (void)in_sizes; (void)n_in; (void)out_size;
    const float* x    = (const float*)d_in[0];
    const float* ic   = (const float*)d_in[1];
    const float* W    = (const float*)d_in[2];
    const float* U    = (const float*)d_in[3];
    const float* b    = (const float*)d_in[4];
    const float* W_ih = (const float*)d_in[5];
    const float* b_ih = (const float*)d_in[6];
    const float* W_ic = (const float*)d_in[7];
    const float* b_ic = (const float*)d_in[8];
    const float* W_bn = (const float*)d_in[9];
    const float* W_pc = (const float*)d_in[10];
    const float* b_pc = (const float*)d_in[11];
    const float* W_hd = (const float*)d_in[12];
    const float* b_hd = (const float*)d_in[13];

    float* out = (float*)d_out;
    const size_t TB = (size_t)T_STEPS * BATCH;
    float* out_hd = out;
    float* out_pc = out_hd + TB * NHD;
    float* out_bn = out_pc + TB * NPC;
    float* out_h  = out_bn + TB * NBNECK;
    float* out_c  = out_h  + TB * HS;

    cudaFuncSetAttribute(lstm_kernel,  cudaFuncAttributeMaxDynamicSharedMemorySize, K1_SMEMB);
    cudaFuncSetAttribute(heads_kernel, cudaFuncAttributeMaxDynamicSharedMemorySize, K2_SMEMB);

    lstm_kernel<<<BATCH / 8, 256, K1_SMEMB>>>(x, ic, W, U, b, W_ih, b_ih, W_ic, b_ic,
                                              out_h, out_c);
    heads_kernel<<<(int)(TB / 64), 256, K2_SMEMB>>>(out_h, W_bn, W_pc, b_pc, W_hd, b_hd,
                                                    out_hd, out_pc, out_bn);
}